// round 13
// baseline (speedup 1.0000x reference)
#include <cuda_runtime.h>
#include <cuda_bf16.h>
#include <cstdint>

#define NN 50000
#define NE 300000
#define NG 128
#define HD 256

// ---------------- scratch (device globals; no runtime allocation) ----------------
__device__ __align__(16) float d_h[(size_t)NN * HD];
__device__ __align__(16) float d_agg[(size_t)NN * HD];
__device__ __align__(16) float d_z[(size_t)NN * HD];
__device__ __align__(16) float d_stats[4 * 2 * HD];   // per-layer slots, zeroed in prep
__device__ __align__(16) float d_g[NG * HD];
// bf16 hi/lo planes for GEMM2 A operand (produced by gemm<0> epilogue)
__device__ __align__(16) __nv_bfloat16 d_a1h[(size_t)NN * HD];
__device__ __align__(16) __nv_bfloat16 d_a1l[(size_t)NN * HD];
// pre-split weights, TRANSPOSED [n][k]: [layer][mat][part hi/lo][256*256]
__device__ __align__(16) __nv_bfloat16 d_wbf[4][2][2][65536];

// ---------------- helpers ----------------
__device__ __forceinline__ uint32_t smem_u32(const void* p) {
    uint32_t a;
    asm("{ .reg .u64 t; cvta.to.shared.u64 t, %1; cvt.u32.u64 %0, t; }" : "=r"(a) : "l"(p));
    return a;
}
__device__ __forceinline__ void cp16(uint32_t dst, const void* src, int srcsize) {
    asm volatile("cp.async.cg.shared.global [%0], [%1], 16, %2;"
                 :: "r"(dst), "l"(src), "r"(srcsize) : "memory");
}
#define CP_COMMIT() asm volatile("cp.async.commit_group;" ::: "memory")
#define CP_WAIT(n)  asm volatile("cp.async.wait_group %0;" :: "n"(n) : "memory")

__device__ __forceinline__ void ldsm_x4(uint32_t& r0, uint32_t& r1, uint32_t& r2, uint32_t& r3, uint32_t a) {
    asm volatile("ldmatrix.sync.aligned.m8n8.x4.shared.b16 {%0,%1,%2,%3}, [%4];"
                 : "=r"(r0), "=r"(r1), "=r"(r2), "=r"(r3) : "r"(a));
}
__device__ __forceinline__ void mma_bf16(float* d, const uint32_t* a, const uint32_t* b) {
    asm volatile("mma.sync.aligned.m16n8k16.row.col.f32.bf16.bf16.f32 "
                 "{%0,%1,%2,%3}, {%4,%5,%6,%7}, {%8,%9}, {%0,%1,%2,%3};"
                 : "+f"(d[0]), "+f"(d[1]), "+f"(d[2]), "+f"(d[3])
                 : "r"(a[0]), "r"(a[1]), "r"(a[2]), "r"(a[3]), "r"(b[0]), "r"(b[1]));
}
__device__ __forceinline__ void red4(float4* p, float4 v) {
    asm volatile("red.global.add.v4.f32 [%0], {%1,%2,%3,%4};"
                 :: "l"(p), "f"(v.x), "f"(v.y), "f"(v.z), "f"(v.w) : "memory");
}
__device__ __forceinline__ uint32_t b2u(__nv_bfloat162 v) { return *(uint32_t*)&v; }
__device__ __forceinline__ unsigned long long pack2(float lo, float hi) {
    unsigned long long r;
    asm("mov.b64 %0, {%1, %2};" : "=l"(r) : "f"(lo), "f"(hi));
    return r;
}
__device__ __forceinline__ void fma2(unsigned long long& d, unsigned long long a, unsigned long long b) {
    asm("fma.rn.f32x2 %0, %1, %2, %0;" : "+l"(d) : "l"(a), "l"(b));
}
__device__ __forceinline__ float2 unpack2(unsigned long long v) {
    float2 f;
    asm("mov.b64 {%0, %1}, %2;" : "=f"(f.x), "=f"(f.y) : "l"(v));
    return f;
}
// split one fp32 pair into bf16x2 hi + bf16x2 lo (identical rounding to split_a0)
__device__ __forceinline__ void split2(float a, float b, uint32_t& hi, uint32_t& lo) {
    __nv_bfloat162 h = __floats2bfloat162_rn(a, b);
    __nv_bfloat162 l = __floats2bfloat162_rn(a - __bfloat162float(h.x), b - __bfloat162float(h.y));
    hi = b2u(h); lo = b2u(l);
}

// ---------------- fused prep: node embed (0..781) + weight split (782..789) + zero (790) ----
__global__ void __launch_bounds__(256) prep(
    const float* __restrict__ x, const float* __restrict__ node_w, const float* __restrict__ node_b,
    const float* __restrict__ mw1, const float* __restrict__ mw2) {
    if (blockIdx.x < 782) {
        int f = threadIdx.x;
        float wreg[32];
#pragma unroll
        for (int k = 0; k < 32; k++) wreg[k] = node_w[k * HD + f];
        float bf = node_b[f];
        __shared__ float xs[8][32];
        int base = blockIdx.x * 64;
        for (int nb = 0; nb < 64; nb += 8) {
            int ni = threadIdx.x >> 5, kk = threadIdx.x & 31;
            int node = base + nb + ni;
            __syncthreads();
            xs[ni][kk] = (node < NN) ? x[(size_t)node * 32 + kk] : 0.f;
            __syncthreads();
            for (int j = 0; j < 8; j++) {
                int n2 = base + nb + j;
                if (n2 >= NN) break;
                float acc = bf;
#pragma unroll
                for (int k = 0; k < 32; k++) acc = fmaf(xs[j][k], wreg[k], acc);
                d_h[(size_t)n2 * HD + f] = acc;
                d_agg[(size_t)n2 * HD + f] = acc;
            }
        }
    } else if (blockIdx.x < 790) {
        int b = blockIdx.x - 782;
        int mat = b & 1, l = b >> 1;
        const float* W = (mat ? mw2 : mw1) + (size_t)l * HD * HD;
        __nv_bfloat16* dh = &d_wbf[l][mat][0][0];
        __nv_bfloat16* dl = &d_wbf[l][mat][1][0];
        int k = threadIdx.x;
        for (int n = 0; n < 256; n++) {
            float w0 = W[(size_t)k * HD + n];
            __nv_bfloat16 hi = __float2bfloat16_rn(w0);
            __nv_bfloat16 lo = __float2bfloat16_rn(w0 - __bfloat162float(hi));
            dh[n * HD + k] = hi;
            dl[n * HD + k] = lo;
        }
    } else {
        int t = threadIdx.x;
        for (int i = t; i < NG * HD; i += 256) d_g[i] = 0.f;
        for (int i = t; i < 4 * 2 * HD; i += 256) d_stats[i] = 0.f;
    }
}

// ---------------- fused edge message: agg[dst] += relu(h[src] + edge_attr@ew + eb) --------
__global__ void __launch_bounds__(256) edge_msg_f(
    const int* __restrict__ ei, const float* __restrict__ eattr,
    const float* __restrict__ ew, const float* __restrict__ eb) {
    __shared__ float ea_s[256][16];
    __shared__ int se[256], de[256];
    int tid = threadIdx.x;
    int e0 = blockIdx.x * 256;
    int colg = tid & 63;
    int grp = tid >> 6;
    int nE = NE - e0; if (nE > 256) nE = 256;

#pragma unroll
    for (int i = 0; i < 4; i++) {
        int idx = tid + i * 256;
        int e = idx >> 2, q = idx & 3;
        if (e < nE)
            *(float4*)&ea_s[e][q * 4] = ((const float4*)(eattr + (size_t)(e0 + e) * 16))[q];
    }
    if (tid < nE) se[tid] = ei[e0 + tid];
    if (tid < nE) de[tid] = ei[NE + e0 + tid];

    unsigned long long w2[16][2];
#pragma unroll
    for (int k = 0; k < 16; k++) {
        float4 wv = *(const float4*)(ew + k * HD + colg * 4);
        w2[k][0] = pack2(wv.x, wv.y);
        w2[k][1] = pack2(wv.z, wv.w);
    }
    float4 bv = *(const float4*)(eb + colg * 4);
    unsigned long long bias01 = pack2(bv.x, bv.y), bias23 = pack2(bv.z, bv.w);
    __syncthreads();

    int nloc = nE - grp * 64;
    if (nloc > 64) nloc = 64;
    for (int ee = 0; ee < nloc; ee++) {
        int e = grp * 64 + ee;
        unsigned long long a01 = bias01, a23 = bias23;
#pragma unroll
        for (int q = 0; q < 4; q++) {
            float4 ev = *(const float4*)&ea_s[e][q * 4];
            unsigned long long p0 = pack2(ev.x, ev.x);
            fma2(a01, p0, w2[q * 4 + 0][0]); fma2(a23, p0, w2[q * 4 + 0][1]);
            unsigned long long p1 = pack2(ev.y, ev.y);
            fma2(a01, p1, w2[q * 4 + 1][0]); fma2(a23, p1, w2[q * 4 + 1][1]);
            unsigned long long p2 = pack2(ev.z, ev.z);
            fma2(a01, p2, w2[q * 4 + 2][0]); fma2(a23, p2, w2[q * 4 + 2][1]);
            unsigned long long p3 = pack2(ev.w, ev.w);
            fma2(a01, p3, w2[q * 4 + 3][0]); fma2(a23, p3, w2[q * 4 + 3][1]);
        }
        int src = se[e], dst = de[e];
        float4 hv = *(const float4*)(d_h + (size_t)src * HD + colg * 4);
        float2 f01 = unpack2(a01), f23 = unpack2(a23);
        float4 m;
        m.x = fmaxf(hv.x + f01.x, 0.f);
        m.y = fmaxf(hv.y + f01.y, 0.f);
        m.z = fmaxf(hv.z + f23.x, 0.f);
        m.w = fmaxf(hv.w + f23.y, 0.f);
        red4((float4*)(d_agg + (size_t)dst * HD) + colg, m);
    }
}

// ---------------- mma.sync bf16-split GEMM: K32, 2-stage, warp-staggered k-halves -------
// MODE 0: A = d_agg fp32, split to bf16 hi/lo IN the producer (LDG+cvt+STS); relu; out
//         split -> d_a1h/l.
// MODE 1: A = d_a1h/l via cp.async; out fp32 -> d_z.
#define AHI 0
#define ALO 10240
#define BHI 20480
#define BLO 30720
#define STG 40960
#define ROWB 80

template <int MODE>
__global__ void __launch_bounds__(256) gemm_mma(int l, int mat, const float* __restrict__ bias) {
    const __nv_bfloat16* __restrict__ Wh = &d_wbf[l][mat][0][0];
    const __nv_bfloat16* __restrict__ Wl = &d_wbf[l][mat][1][0];

    extern __shared__ char smbuf[];
    uint32_t base = smem_u32(smbuf);
    int tid = threadIdx.x, lane = tid & 31, wid = tid >> 5;
    int wm = wid & 1, wn = wid >> 1;
    int ks0 = wid & 1;
    int m0 = blockIdx.x * 128, n0 = blockIdx.y * 128;

    float acc[4][4][4];
#pragma unroll
    for (int a = 0; a < 4; a++)
#pragma unroll
        for (int b = 0; b < 4; b++)
#pragma unroll
            for (int c = 0; c < 4; c++) acc[a][b][c] = 0.f;

    auto load_stage = [&](int c, int s) {
#pragma unroll
        for (int it = 0; it < 2; it++) {
            int idx = tid + it * 256;
            int row = idx >> 2, g = idx & 3;
            uint32_t dd = base + s * STG + row * ROWB + g * 16;
            size_t koff = (size_t)c * 32 + g * 8;
            int m = m0 + row;
            if (MODE == 0) {
                // fp32 A -> bf16 hi/lo split in-register, STS to same layout
                int mc = (m < NN) ? m : 0;               // clamp (masked rows, finite data)
                const float4* p = (const float4*)(d_agg + (size_t)mc * HD + koff);
                float4 v0 = p[0], v1 = p[1];
                uint32_t h0, h1, h2, h3, l0, l1, l2, l3;
                split2(v0.x, v0.y, h0, l0);
                split2(v0.z, v0.w, h1, l1);
                split2(v1.x, v1.y, h2, l2);
                split2(v1.z, v1.w, h3, l3);
                *(uint4*)(smbuf + (dd - base) + AHI) = make_uint4(h0, h1, h2, h3);
                *(uint4*)(smbuf + (dd - base) + ALO) = make_uint4(l0, l1, l2, l3);
            } else {
                int ok = (m < NN) ? 16 : 0;
                size_t so = (size_t)(ok ? m : 0) * HD + koff;
                cp16(dd + AHI, d_a1h + so, ok);
                cp16(dd + ALO, d_a1l + so, ok);
            }
            size_t wo = (size_t)(n0 + row) * HD + koff;
            cp16(dd + BHI, Wh + wo, 16);
            cp16(dd + BLO, Wl + wo, 16);
        }
    };

    load_stage(0, 0); CP_COMMIT();

    int buf = 0;
    for (int c = 0; c < 8; c++) {
        CP_WAIT(0);
        __syncthreads();
        if (c < 7) {
            load_stage(c + 1, buf ^ 1);
            CP_COMMIT();
        }
        uint32_t sb = base + buf * STG;

#pragma unroll
        for (int kk = 0; kk < 2; kk++) {
            int ks = ks0 ^ kk;
            uint32_t arow = (uint32_t)(wm * 64 + (lane & 15)) * ROWB + ks * 32 + (uint32_t)(lane >> 4) * 16;
            uint32_t bbase = (uint32_t)(wn * 32 + ((lane >> 4) << 3) + (lane & 7)) * ROWB
                           + ks * 32 + (uint32_t)((lane >> 3) & 1) * 16;

            uint32_t bh[4][2];
#pragma unroll
            for (int pr = 0; pr < 2; pr++) {
                uint32_t ba = sb + bbase + pr * (16 * ROWB);
                ldsm_x4(bh[pr * 2][0], bh[pr * 2][1], bh[pr * 2 + 1][0], bh[pr * 2 + 1][1], ba + BHI);
            }
            uint32_t ah[4][4];
#pragma unroll
            for (int mt = 0; mt < 4; mt++) {
                uint32_t aa = sb + arow + mt * (16 * ROWB);
                ldsm_x4(ah[mt][0], ah[mt][1], ah[mt][2], ah[mt][3], aa + AHI);
            }
#pragma unroll
            for (int mt = 0; mt < 4; mt++)
#pragma unroll
                for (int nt = 0; nt < 4; nt++) mma_bf16(acc[mt][nt], ah[mt], bh[nt]);
#pragma unroll
            for (int mt = 0; mt < 4; mt++) {
                uint32_t alr[4];
                uint32_t aa = sb + arow + mt * (16 * ROWB);
                ldsm_x4(alr[0], alr[1], alr[2], alr[3], aa + ALO);
#pragma unroll
                for (int nt = 0; nt < 4; nt++) mma_bf16(acc[mt][nt], alr, bh[nt]);
            }
            uint32_t bl[4][2];
#pragma unroll
            for (int pr = 0; pr < 2; pr++) {
                uint32_t ba = sb + bbase + pr * (16 * ROWB);
                ldsm_x4(bl[pr * 2][0], bl[pr * 2][1], bl[pr * 2 + 1][0], bl[pr * 2 + 1][1], ba + BLO);
            }
#pragma unroll
            for (int mt = 0; mt < 4; mt++)
#pragma unroll
                for (int nt = 0; nt < 4; nt++) mma_bf16(acc[mt][nt], ah[mt], bl[nt]);
        }
        buf ^= 1;
    }

    // epilogue
    int r = lane >> 2, c2 = (lane & 3) * 2;
#pragma unroll
    for (int mt = 0; mt < 4; mt++) {
        int row0 = m0 + wm * 64 + mt * 16 + r;
#pragma unroll
        for (int nt = 0; nt < 4; nt++) {
            int col = n0 + wn * 32 + nt * 8 + c2;
            float bv0 = bias[col], bv1 = bias[col + 1];
#pragma unroll
            for (int h = 0; h < 2; h++) {
                int row = row0 + h * 8;
                if (row < NN) {
                    float v0 = acc[mt][nt][2 * h] + bv0;
                    float v1 = acc[mt][nt][2 * h + 1] + bv1;
                    if (MODE == 0) {
                        v0 = fmaxf(v0, 0.f);
                        v1 = fmaxf(v1, 0.f);
                        uint32_t hi, lo;
                        split2(v0, v1, hi, lo);
                        *(uint32_t*)(d_a1h + (size_t)row * HD + col) = hi;
                        *(uint32_t*)(d_a1l + (size_t)row * HD + col) = lo;
                    } else {
                        *(float2*)(d_z + (size_t)row * HD + col) = make_float2(v0, v1);
                    }
                }
            }
        }
    }
}

// ---------------- batchnorm ----------------
__global__ void __launch_bounds__(256) bn_stats(int l) {
    int col = threadIdx.x;
    int r0 = blockIdx.x * 200;
    float s = 0.f, q = 0.f;
    for (int r = r0; r < r0 + 200; r++) {
        float v = d_z[(size_t)r * HD + col];
        s += v; q += v * v;
    }
    atomicAdd(&d_stats[l * 512 + col], s);
    atomicAdd(&d_stats[l * 512 + HD + col], q);
}

__global__ void __launch_bounds__(256) bn_apply(int l, int write_agg,
                                                const float* __restrict__ gamma,
                                                const float* __restrict__ beta) {
    __shared__ float sc_s[256], sh_s[256];
    int tid = threadIdx.x;
    {
        float s = d_stats[l * 512 + tid], q = d_stats[l * 512 + HD + tid];
        float mu = s * (1.0f / NN);
        float var = q * (1.0f / NN) - mu * mu;
        float sc = gamma[tid] * rsqrtf(var + 1e-5f);
        sc_s[tid] = sc;
        sh_s[tid] = beta[tid] - mu * sc;
    }
    __syncthreads();
    size_t i = (size_t)blockIdx.x * 256 + tid;
    int f4 = (int)(i & 63) * 4;
    float4 z = ((const float4*)d_z)[i];
    float4 sc = *(const float4*)&sc_s[f4];
    float4 sh = *(const float4*)&sh_s[f4];
    float4 v;
    v.x = fmaxf(fmaf(z.x, sc.x, sh.x), 0.f);
    v.y = fmaxf(fmaf(z.y, sc.y, sh.y), 0.f);
    v.z = fmaxf(fmaf(z.z, sc.z, sh.z), 0.f);
    v.w = fmaxf(fmaf(z.w, sc.w, sh.w), 0.f);
    ((float4*)d_h)[i] = v;
    if (write_agg) ((float4*)d_agg)[i] = v;
}

// ---------------- pooling + head ----------------
__global__ void __launch_bounds__(256) pool(const int* __restrict__ batch) {
    int w = (blockIdx.x * 256 + threadIdx.x) >> 5;
    int lane = threadIdx.x & 31;
    if (w >= NN) return;
    int g = batch[w];
    const float4* hp = (const float4*)(d_h + (size_t)w * HD);
    float4* gp = (float4*)(d_g + (size_t)g * HD);
#pragma unroll
    for (int c = 0; c < 2; c++) red4(gp + lane + c * 32, hp[lane + c * 32]);
}

__global__ void __launch_bounds__(128) head(
    const float* __restrict__ w1, const float* __restrict__ b1,
    const float* __restrict__ w2, const float* __restrict__ b2,
    float* __restrict__ out) {
    __shared__ float gs[256];
    __shared__ float hs[128];
    int gid = blockIdx.x, t = threadIdx.x;
    gs[t] = d_g[gid * HD + t];
    gs[t + 128] = d_g[gid * HD + t + 128];
    __syncthreads();
    float acc = b1[t];
#pragma unroll 8
    for (int k = 0; k < 256; k++) acc = fmaf(gs[k], w1[k * 128 + t], acc);
    hs[t] = fmaxf(acc, 0.f);
    __syncthreads();
    if (t < 12) {
        float o = b2[t];
#pragma unroll 8
        for (int k = 0; k < 128; k++) o = fmaf(hs[k], w2[k * 12 + t], o);
        out[gid * 12 + t] = o;
    }
}

// ---------------- launch ----------------
extern "C" void kernel_launch(void* const* d_in, const int* in_sizes, int n_in,
                              void* d_out, int out_size) {
    const float* x      = (const float*)d_in[0];
    const int*   ei     = (const int*)d_in[1];
    const int*   batch  = (const int*)d_in[2];
    const float* eattr  = (const float*)d_in[3];
    const float* node_w = (const float*)d_in[4];
    const float* node_b = (const float*)d_in[5];
    const float* edge_w = (const float*)d_in[6];
    const float* edge_b = (const float*)d_in[7];
    const float* mw1    = (const float*)d_in[8];
    const float* mb1    = (const float*)d_in[9];
    const float* mw2    = (const float*)d_in[10];
    const float* mb2    = (const float*)d_in[11];
    const float* gamma  = (const float*)d_in[12];
    const float* beta   = (const float*)d_in[13];
    const float* hw1    = (const float*)d_in[14];
    const float* hb1    = (const float*)d_in[15];
    const float* hw2    = (const float*)d_in[16];
    const float* hb2    = (const float*)d_in[17];
    float* out = (float*)d_out;

    const int GEMM_SMEM = 2 * STG;  // 81920 bytes -> 2 CTAs/SM
    static bool attr_done = false;
    if (!attr_done) {
        cudaFuncSetAttribute(gemm_mma<0>, cudaFuncAttributeMaxDynamicSharedMemorySize, GEMM_SMEM);
        cudaFuncSetAttribute(gemm_mma<1>, cudaFuncAttributeMaxDynamicSharedMemorySize, GEMM_SMEM);
        attr_done = true;
    }

    prep<<<791, 256>>>(x, node_w, node_b, mw1, mw2);

    dim3 gg((NN + 127) / 128, 2);
    for (int l = 0; l < 4; l++) {
        edge_msg_f<<<(NE + 255) / 256, 256>>>(ei, eattr, edge_w, edge_b);
        gemm_mma<0><<<gg, 256, GEMM_SMEM>>>(l, 0, mb1 + l * HD);
        gemm_mma<1><<<gg, 256, GEMM_SMEM>>>(l, 1, mb2 + l * HD);
        bn_stats<<<250, 256>>>(l);
        bn_apply<<<(NN * 64) / 256, 256>>>(l, l < 3 ? 1 : 0, gamma + l * HD, beta + l * HD);
    }

    pool<<<(NN + 7) / 8, 256>>>(batch);
    head<<<NG, 128>>>(hw1, hb1, hw2, hb2, out);
}

// round 14
// speedup vs baseline: 1.0752x; 1.0752x over previous
#include <cuda_runtime.h>
#include <cuda_bf16.h>
#include <cstdint>

#define NN 50000
#define NE 300000
#define NG 128
#define HD 256

// ---------------- scratch (device globals; no runtime allocation) ----------------
__device__ __align__(16) float d_h[(size_t)NN * HD];
__device__ __align__(16) float d_agg[(size_t)NN * HD];
__device__ __align__(16) float d_z[(size_t)NN * HD];
__device__ __align__(16) float d_stats[4 * 2 * HD];   // per-layer slots, zeroed in prep
__device__ __align__(16) float d_g[NG * HD];
// bf16 hi/lo planes for GEMM2 A operand (produced by gemm<0> epilogue)
__device__ __align__(16) __nv_bfloat16 d_a1h[(size_t)NN * HD];
__device__ __align__(16) __nv_bfloat16 d_a1l[(size_t)NN * HD];
// pre-split weights, TRANSPOSED [n][k]: [layer][mat][part hi/lo][256*256]
__device__ __align__(16) __nv_bfloat16 d_wbf[4][2][2][65536];

// ---------------- helpers ----------------
__device__ __forceinline__ uint32_t smem_u32(const void* p) {
    uint32_t a;
    asm("{ .reg .u64 t; cvta.to.shared.u64 t, %1; cvt.u32.u64 %0, t; }" : "=r"(a) : "l"(p));
    return a;
}
__device__ __forceinline__ void cp16(uint32_t dst, const void* src, int srcsize) {
    asm volatile("cp.async.cg.shared.global [%0], [%1], 16, %2;"
                 :: "r"(dst), "l"(src), "r"(srcsize) : "memory");
}
#define CP_COMMIT() asm volatile("cp.async.commit_group;" ::: "memory")
#define CP_WAIT(n)  asm volatile("cp.async.wait_group %0;" :: "n"(n) : "memory")

__device__ __forceinline__ void ldsm_x4(uint32_t& r0, uint32_t& r1, uint32_t& r2, uint32_t& r3, uint32_t a) {
    asm volatile("ldmatrix.sync.aligned.m8n8.x4.shared.b16 {%0,%1,%2,%3}, [%4];"
                 : "=r"(r0), "=r"(r1), "=r"(r2), "=r"(r3) : "r"(a));
}
__device__ __forceinline__ void mma_bf16(float* d, const uint32_t* a, const uint32_t* b) {
    asm volatile("mma.sync.aligned.m16n8k16.row.col.f32.bf16.bf16.f32 "
                 "{%0,%1,%2,%3}, {%4,%5,%6,%7}, {%8,%9}, {%0,%1,%2,%3};"
                 : "+f"(d[0]), "+f"(d[1]), "+f"(d[2]), "+f"(d[3])
                 : "r"(a[0]), "r"(a[1]), "r"(a[2]), "r"(a[3]), "r"(b[0]), "r"(b[1]));
}
__device__ __forceinline__ void red4(float4* p, float4 v) {
    asm volatile("red.global.add.v4.f32 [%0], {%1,%2,%3,%4};"
                 :: "l"(p), "f"(v.x), "f"(v.y), "f"(v.z), "f"(v.w) : "memory");
}
__device__ __forceinline__ uint32_t b2u(__nv_bfloat162 v) { return *(uint32_t*)&v; }
__device__ __forceinline__ unsigned long long pack2(float lo, float hi) {
    unsigned long long r;
    asm("mov.b64 %0, {%1, %2};" : "=l"(r) : "f"(lo), "f"(hi));
    return r;
}
__device__ __forceinline__ void fma2(unsigned long long& d, unsigned long long a, unsigned long long b) {
    asm("fma.rn.f32x2 %0, %1, %2, %0;" : "+l"(d) : "l"(a), "l"(b));
}
__device__ __forceinline__ float2 unpack2(unsigned long long v) {
    float2 f;
    asm("mov.b64 {%0, %1}, %2;" : "=f"(f.x), "=f"(f.y) : "l"(v));
    return f;
}
// split one fp32 pair into bf16x2 hi + bf16x2 lo (identical rounding to old split_a0)
__device__ __forceinline__ void split2(float a, float b, uint32_t& hi, uint32_t& lo) {
    __nv_bfloat162 h = __floats2bfloat162_rn(a, b);
    __nv_bfloat162 l = __floats2bfloat162_rn(a - __bfloat162float(h.x), b - __bfloat162float(h.y));
    hi = b2u(h); lo = b2u(l);
}

// ---------------- fused prep: node embed (0..781) + weight split (782..789) + zero (790) ----
__global__ void __launch_bounds__(256) prep(
    const float* __restrict__ x, const float* __restrict__ node_w, const float* __restrict__ node_b,
    const float* __restrict__ mw1, const float* __restrict__ mw2) {
    if (blockIdx.x < 782) {
        int f = threadIdx.x;
        float wreg[32];
#pragma unroll
        for (int k = 0; k < 32; k++) wreg[k] = node_w[k * HD + f];
        float bf = node_b[f];
        __shared__ float xs[8][32];
        int base = blockIdx.x * 64;
        for (int nb = 0; nb < 64; nb += 8) {
            int ni = threadIdx.x >> 5, kk = threadIdx.x & 31;
            int node = base + nb + ni;
            __syncthreads();
            xs[ni][kk] = (node < NN) ? x[(size_t)node * 32 + kk] : 0.f;
            __syncthreads();
            for (int j = 0; j < 8; j++) {
                int n2 = base + nb + j;
                if (n2 >= NN) break;
                float acc = bf;
#pragma unroll
                for (int k = 0; k < 32; k++) acc = fmaf(xs[j][k], wreg[k], acc);
                d_h[(size_t)n2 * HD + f] = acc;
                d_agg[(size_t)n2 * HD + f] = acc;
            }
        }
    } else if (blockIdx.x < 790) {
        int b = blockIdx.x - 782;
        int mat = b & 1, l = b >> 1;
        const float* W = (mat ? mw2 : mw1) + (size_t)l * HD * HD;
        __nv_bfloat16* dh = &d_wbf[l][mat][0][0];
        __nv_bfloat16* dl = &d_wbf[l][mat][1][0];
        int k = threadIdx.x;
        for (int n = 0; n < 256; n++) {
            float w0 = W[(size_t)k * HD + n];
            __nv_bfloat16 hi = __float2bfloat16_rn(w0);
            __nv_bfloat16 lo = __float2bfloat16_rn(w0 - __bfloat162float(hi));
            dh[n * HD + k] = hi;
            dl[n * HD + k] = lo;
        }
    } else {
        int t = threadIdx.x;
        for (int i = t; i < NG * HD; i += 256) d_g[i] = 0.f;
        for (int i = t; i < 4 * 2 * HD; i += 256) d_stats[i] = 0.f;
    }
}

// ---------------- fused edge message: agg[dst] += relu(h[src] + edge_attr@ew + eb) --------
__global__ void __launch_bounds__(256) edge_msg_f(
    const int* __restrict__ ei, const float* __restrict__ eattr,
    const float* __restrict__ ew, const float* __restrict__ eb) {
    __shared__ float ea_s[256][16];
    __shared__ int se[256], de[256];
    int tid = threadIdx.x;
    int e0 = blockIdx.x * 256;
    int colg = tid & 63;
    int grp = tid >> 6;
    int nE = NE - e0; if (nE > 256) nE = 256;

#pragma unroll
    for (int i = 0; i < 4; i++) {
        int idx = tid + i * 256;
        int e = idx >> 2, q = idx & 3;
        if (e < nE)
            *(float4*)&ea_s[e][q * 4] = ((const float4*)(eattr + (size_t)(e0 + e) * 16))[q];
    }
    if (tid < nE) se[tid] = ei[e0 + tid];
    if (tid < nE) de[tid] = ei[NE + e0 + tid];

    unsigned long long w2[16][2];
#pragma unroll
    for (int k = 0; k < 16; k++) {
        float4 wv = *(const float4*)(ew + k * HD + colg * 4);
        w2[k][0] = pack2(wv.x, wv.y);
        w2[k][1] = pack2(wv.z, wv.w);
    }
    float4 bv = *(const float4*)(eb + colg * 4);
    unsigned long long bias01 = pack2(bv.x, bv.y), bias23 = pack2(bv.z, bv.w);
    __syncthreads();

    int nloc = nE - grp * 64;
    if (nloc > 64) nloc = 64;
    for (int ee = 0; ee < nloc; ee++) {
        int e = grp * 64 + ee;
        unsigned long long a01 = bias01, a23 = bias23;
#pragma unroll
        for (int q = 0; q < 4; q++) {
            float4 ev = *(const float4*)&ea_s[e][q * 4];
            unsigned long long p0 = pack2(ev.x, ev.x);
            fma2(a01, p0, w2[q * 4 + 0][0]); fma2(a23, p0, w2[q * 4 + 0][1]);
            unsigned long long p1 = pack2(ev.y, ev.y);
            fma2(a01, p1, w2[q * 4 + 1][0]); fma2(a23, p1, w2[q * 4 + 1][1]);
            unsigned long long p2 = pack2(ev.z, ev.z);
            fma2(a01, p2, w2[q * 4 + 2][0]); fma2(a23, p2, w2[q * 4 + 2][1]);
            unsigned long long p3 = pack2(ev.w, ev.w);
            fma2(a01, p3, w2[q * 4 + 3][0]); fma2(a23, p3, w2[q * 4 + 3][1]);
        }
        int src = se[e], dst = de[e];
        float4 hv = *(const float4*)(d_h + (size_t)src * HD + colg * 4);
        float2 f01 = unpack2(a01), f23 = unpack2(a23);
        float4 m;
        m.x = fmaxf(hv.x + f01.x, 0.f);
        m.y = fmaxf(hv.y + f01.y, 0.f);
        m.z = fmaxf(hv.z + f23.x, 0.f);
        m.w = fmaxf(hv.w + f23.y, 0.f);
        red4((float4*)(d_agg + (size_t)dst * HD) + colg, m);
    }
}

// ---------------- mma.sync bf16-split GEMM: K32, 2-stage, warp-staggered k-halves -------
// MODE 0: A = d_agg fp32 via cp.async into staging; SMEM convert -> bf16 hi/lo planes;
//         relu; out split -> d_a1h/l.
// MODE 1: A = d_a1h/l via cp.async directly; out fp32 -> d_z.
// Stage layouts (per stage):
//   MODE 0: AF32 @0 (16384B, slot-linear), AHI @16384, ALO @26624, BHI @36864, BLO @47104; STG=57344
//   MODE 1: AHI @0, ALO @10240, BHI @20480, BLO @30720; STG=40960
#define ROWB 80

template <int MODE>
__global__ void __launch_bounds__(256) gemm_mma(int l, int mat, const float* __restrict__ bias) {
    constexpr int AF32 = 0;
    constexpr int AHI = (MODE == 0) ? 16384 : 0;
    constexpr int ALO = AHI + 10240;
    constexpr int BHI = ALO + 10240;
    constexpr int BLO = BHI + 10240;
    constexpr int STG = BLO + 10240;

    const __nv_bfloat16* __restrict__ Wh = &d_wbf[l][mat][0][0];
    const __nv_bfloat16* __restrict__ Wl = &d_wbf[l][mat][1][0];

    extern __shared__ char smbuf[];
    uint32_t base = smem_u32(smbuf);
    int tid = threadIdx.x, lane = tid & 31, wid = tid >> 5;
    int wm = wid & 1, wn = wid >> 1;
    int ks0 = wid & 1;
    int m0 = blockIdx.x * 128, n0 = blockIdx.y * 128;

    float acc[4][4][4];
#pragma unroll
    for (int a = 0; a < 4; a++)
#pragma unroll
        for (int b = 0; b < 4; b++)
#pragma unroll
            for (int c = 0; c < 4; c++) acc[a][b][c] = 0.f;

    auto load_stage = [&](int c, int s) {
        if (MODE == 0) {
            // fp32 A into slot-linear staging: slot = row*8 + g (g = 4-float group)
#pragma unroll
            for (int it = 0; it < 4; it++) {
                int slot = tid + it * 256;            // 0..1023
                int row = slot >> 3, g = slot & 7;
                int m = m0 + row;
                int ok = (m < NN) ? 16 : 0;
                size_t so = (size_t)(ok ? m : 0) * HD + c * 32 + g * 4;
                cp16(base + s * STG + AF32 + slot * 16, d_agg + so, ok);
            }
        } else {
#pragma unroll
            for (int it = 0; it < 2; it++) {
                int idx = tid + it * 256;
                int row = idx >> 2, g = idx & 3;
                uint32_t dd = base + s * STG + row * ROWB + g * 16;
                size_t koff = (size_t)c * 32 + g * 8;
                int m = m0 + row;
                int ok = (m < NN) ? 16 : 0;
                size_t so = (size_t)(ok ? m : 0) * HD + koff;
                cp16(dd + AHI, d_a1h + so, ok);
                cp16(dd + ALO, d_a1l + so, ok);
            }
        }
#pragma unroll
        for (int it = 0; it < 2; it++) {
            int idx = tid + it * 256;
            int row = idx >> 2, g = idx & 3;
            uint32_t dd = base + s * STG + row * ROWB + g * 16;
            size_t koff = (size_t)c * 32 + g * 8;
            size_t wo = (size_t)(n0 + row) * HD + koff;
            cp16(dd + BHI, Wh + wo, 16);
            cp16(dd + BLO, Wl + wo, 16);
        }
    };

    load_stage(0, 0); CP_COMMIT();

    int buf = 0;
    for (int c = 0; c < 8; c++) {
        CP_WAIT(0);
        __syncthreads();
        if (c < 7) {
            load_stage(c + 1, buf ^ 1);
            CP_COMMIT();
        }
        uint32_t sb = base + buf * STG;

        if (MODE == 0) {
            // convert staged fp32 -> bf16 hi/lo planes (slot-linear read: conflict-free)
            char* stg = smbuf + buf * STG;
#pragma unroll
            for (int it = 0; it < 4; it++) {
                int slot = tid + it * 256;
                int row = slot >> 3, g = slot & 7;
                float4 v = *(const float4*)(stg + AF32 + slot * 16);
                uint32_t h0, h1, l0, l1;
                split2(v.x, v.y, h0, l0);
                split2(v.z, v.w, h1, l1);
                uint32_t off = (uint32_t)row * ROWB + g * 8;
                *(uint2*)(stg + AHI + off) = make_uint2(h0, h1);
                *(uint2*)(stg + ALO + off) = make_uint2(l0, l1);
            }
            __syncthreads();
        }

#pragma unroll
        for (int kk = 0; kk < 2; kk++) {
            int ks = ks0 ^ kk;
            uint32_t arow = (uint32_t)(wm * 64 + (lane & 15)) * ROWB + ks * 32 + (uint32_t)(lane >> 4) * 16;
            uint32_t bbase = (uint32_t)(wn * 32 + ((lane >> 4) << 3) + (lane & 7)) * ROWB
                           + ks * 32 + (uint32_t)((lane >> 3) & 1) * 16;

            uint32_t bh[4][2];
#pragma unroll
            for (int pr = 0; pr < 2; pr++) {
                uint32_t ba = sb + bbase + pr * (16 * ROWB);
                ldsm_x4(bh[pr * 2][0], bh[pr * 2][1], bh[pr * 2 + 1][0], bh[pr * 2 + 1][1], ba + BHI);
            }
            uint32_t ah[4][4];
#pragma unroll
            for (int mt = 0; mt < 4; mt++) {
                uint32_t aa = sb + arow + mt * (16 * ROWB);
                ldsm_x4(ah[mt][0], ah[mt][1], ah[mt][2], ah[mt][3], aa + AHI);
            }
#pragma unroll
            for (int mt = 0; mt < 4; mt++)
#pragma unroll
                for (int nt = 0; nt < 4; nt++) mma_bf16(acc[mt][nt], ah[mt], bh[nt]);
#pragma unroll
            for (int mt = 0; mt < 4; mt++) {
                uint32_t alr[4];
                uint32_t aa = sb + arow + mt * (16 * ROWB);
                ldsm_x4(alr[0], alr[1], alr[2], alr[3], aa + ALO);
#pragma unroll
                for (int nt = 0; nt < 4; nt++) mma_bf16(acc[mt][nt], alr, bh[nt]);
            }
            uint32_t bl[4][2];
#pragma unroll
            for (int pr = 0; pr < 2; pr++) {
                uint32_t ba = sb + bbase + pr * (16 * ROWB);
                ldsm_x4(bl[pr * 2][0], bl[pr * 2][1], bl[pr * 2 + 1][0], bl[pr * 2 + 1][1], ba + BLO);
            }
#pragma unroll
            for (int mt = 0; mt < 4; mt++)
#pragma unroll
                for (int nt = 0; nt < 4; nt++) mma_bf16(acc[mt][nt], ah[mt], bl[nt]);
        }
        buf ^= 1;
    }

    // epilogue
    int r = lane >> 2, c2 = (lane & 3) * 2;
#pragma unroll
    for (int mt = 0; mt < 4; mt++) {
        int row0 = m0 + wm * 64 + mt * 16 + r;
#pragma unroll
        for (int nt = 0; nt < 4; nt++) {
            int col = n0 + wn * 32 + nt * 8 + c2;
            float bv0 = bias[col], bv1 = bias[col + 1];
#pragma unroll
            for (int h = 0; h < 2; h++) {
                int row = row0 + h * 8;
                if (row < NN) {
                    float v0 = acc[mt][nt][2 * h] + bv0;
                    float v1 = acc[mt][nt][2 * h + 1] + bv1;
                    if (MODE == 0) {
                        v0 = fmaxf(v0, 0.f);
                        v1 = fmaxf(v1, 0.f);
                        uint32_t hi, lo;
                        split2(v0, v1, hi, lo);
                        *(uint32_t*)(d_a1h + (size_t)row * HD + col) = hi;
                        *(uint32_t*)(d_a1l + (size_t)row * HD + col) = lo;
                    } else {
                        *(float2*)(d_z + (size_t)row * HD + col) = make_float2(v0, v1);
                    }
                }
            }
        }
    }
}

// ---------------- batchnorm ----------------
__global__ void __launch_bounds__(256) bn_stats(int l) {
    int col = threadIdx.x;
    int r0 = blockIdx.x * 200;
    float s = 0.f, q = 0.f;
    for (int r = r0; r < r0 + 200; r++) {
        float v = d_z[(size_t)r * HD + col];
        s += v; q += v * v;
    }
    atomicAdd(&d_stats[l * 512 + col], s);
    atomicAdd(&d_stats[l * 512 + HD + col], q);
}

__global__ void __launch_bounds__(256) bn_apply(int l, int write_agg,
                                                const float* __restrict__ gamma,
                                                const float* __restrict__ beta) {
    __shared__ float sc_s[256], sh_s[256];
    int tid = threadIdx.x;
    {
        float s = d_stats[l * 512 + tid], q = d_stats[l * 512 + HD + tid];
        float mu = s * (1.0f / NN);
        float var = q * (1.0f / NN) - mu * mu;
        float sc = gamma[tid] * rsqrtf(var + 1e-5f);
        sc_s[tid] = sc;
        sh_s[tid] = beta[tid] - mu * sc;
    }
    __syncthreads();
    size_t i = (size_t)blockIdx.x * 256 + tid;
    int f4 = (int)(i & 63) * 4;
    float4 z = ((const float4*)d_z)[i];
    float4 sc = *(const float4*)&sc_s[f4];
    float4 sh = *(const float4*)&sh_s[f4];
    float4 v;
    v.x = fmaxf(fmaf(z.x, sc.x, sh.x), 0.f);
    v.y = fmaxf(fmaf(z.y, sc.y, sh.y), 0.f);
    v.z = fmaxf(fmaf(z.z, sc.z, sh.z), 0.f);
    v.w = fmaxf(fmaf(z.w, sc.w, sh.w), 0.f);
    ((float4*)d_h)[i] = v;
    if (write_agg) ((float4*)d_agg)[i] = v;
}

// ---------------- pooling + head ----------------
__global__ void __launch_bounds__(256) pool(const int* __restrict__ batch) {
    int w = (blockIdx.x * 256 + threadIdx.x) >> 5;
    int lane = threadIdx.x & 31;
    if (w >= NN) return;
    int g = batch[w];
    const float4* hp = (const float4*)(d_h + (size_t)w * HD);
    float4* gp = (float4*)(d_g + (size_t)g * HD);
#pragma unroll
    for (int c = 0; c < 2; c++) red4(gp + lane + c * 32, hp[lane + c * 32]);
}

__global__ void __launch_bounds__(128) head(
    const float* __restrict__ w1, const float* __restrict__ b1,
    const float* __restrict__ w2, const float* __restrict__ b2,
    float* __restrict__ out) {
    __shared__ float gs[256];
    __shared__ float hs[128];
    int gid = blockIdx.x, t = threadIdx.x;
    gs[t] = d_g[gid * HD + t];
    gs[t + 128] = d_g[gid * HD + t + 128];
    __syncthreads();
    float acc = b1[t];
#pragma unroll 8
    for (int k = 0; k < 256; k++) acc = fmaf(gs[k], w1[k * 128 + t], acc);
    hs[t] = fmaxf(acc, 0.f);
    __syncthreads();
    if (t < 12) {
        float o = b2[t];
#pragma unroll 8
        for (int k = 0; k < 128; k++) o = fmaf(hs[k], w2[k * 12 + t], o);
        out[gid * 12 + t] = o;
    }
}

// ---------------- launch ----------------
extern "C" void kernel_launch(void* const* d_in, const int* in_sizes, int n_in,
                              void* d_out, int out_size) {
    const float* x      = (const float*)d_in[0];
    const int*   ei     = (const int*)d_in[1];
    const int*   batch  = (const int*)d_in[2];
    const float* eattr  = (const float*)d_in[3];
    const float* node_w = (const float*)d_in[4];
    const float* node_b = (const float*)d_in[5];
    const float* edge_w = (const float*)d_in[6];
    const float* edge_b = (const float*)d_in[7];
    const float* mw1    = (const float*)d_in[8];
    const float* mb1    = (const float*)d_in[9];
    const float* mw2    = (const float*)d_in[10];
    const float* mb2    = (const float*)d_in[11];
    const float* gamma  = (const float*)d_in[12];
    const float* beta   = (const float*)d_in[13];
    const float* hw1    = (const float*)d_in[14];
    const float* hb1    = (const float*)d_in[15];
    const float* hw2    = (const float*)d_in[16];
    const float* hb2    = (const float*)d_in[17];
    float* out = (float*)d_out;

    const int SMEM_M0 = 2 * 57344;  // 114688 B -> 2 CTAs/SM (229376 <= 232448)
    const int SMEM_M1 = 2 * 40960;  // 81920 B
    static bool attr_done = false;
    if (!attr_done) {
        cudaFuncSetAttribute(gemm_mma<0>, cudaFuncAttributeMaxDynamicSharedMemorySize, SMEM_M0);
        cudaFuncSetAttribute(gemm_mma<1>, cudaFuncAttributeMaxDynamicSharedMemorySize, SMEM_M1);
        attr_done = true;
    }

    prep<<<791, 256>>>(x, node_w, node_b, mw1, mw2);

    dim3 gg((NN + 127) / 128, 2);
    for (int l = 0; l < 4; l++) {
        edge_msg_f<<<(NE + 255) / 256, 256>>>(ei, eattr, edge_w, edge_b);
        gemm_mma<0><<<gg, 256, SMEM_M0>>>(l, 0, mb1 + l * HD);
        gemm_mma<1><<<gg, 256, SMEM_M1>>>(l, 1, mb2 + l * HD);
        bn_stats<<<250, 256>>>(l);
        bn_apply<<<(NN * 64) / 256, 256>>>(l, l < 3 ? 1 : 0, gamma + l * HD, beta + l * HD);
    }

    pool<<<(NN + 7) / 8, 256>>>(batch);
    head<<<NG, 128>>>(hw1, hb1, hw2, hb2, out);
}